// round 5
// baseline (speedup 1.0000x reference)
#include <cuda_runtime.h>
#include <cuda_bf16.h>
#include <cstdint>
#include <cstddef>

// ---------------- problem constants ----------------
#define BSZ   4
#define SEQ   128
#define TOK   (BSZ*SEQ)        // 512
#define DM    256
#define FF    2048
#define PP    224
#define PED   512
#define PEROW (PP*PED)         // 114688

// output region sizes (floats)
#define SZ_AHID (4LL*192*16*4096)
#define SZ_AINT (4LL*32*16*11008)
#define SZ_BHID (4LL*96*4096*16)
#define SZ_BKV  (4LL*64*1024*16)
#define OFF_AINT (SZ_AHID)
#define OFF_BHID (SZ_AHID+SZ_AINT)
#define OFF_BKV  (OFF_BHID+SZ_BHID)
#define OFF_BINT (OFF_BKV+SZ_BKV)

// ---------------- scratch ----------------
#define S_X     0
#define S_QKV   (S_X    + TOK*DM)
#define S_ATTN  (S_QKV  + TOK*3*DM)
#define S_FF1   (S_ATTN + TOK*DM)
#define S_POOL  (S_FF1  + TOK*FF)
#define S_PE    (S_POOL + BSZ*DM)
#define S_DECHA (S_PE   + BSZ*PEROW)
#define S_DECHB (S_DECHA + 896*DM)
#define S_AB    (S_DECHB + 896*DM)
#define S_BB    (S_AB   + 896*1024)
#define S_PART  (S_BB   + 896*1024)
#define S_TOTAL (S_PART + 4*TOK*DM)

__device__ float g_scratch[S_TOTAL];

// ---------------- grid barrier ----------------
__device__ unsigned g_barcnt;
__device__ unsigned g_barphase;

__device__ __forceinline__ void gsync(int nb) {
    __threadfence();          // publish my writes (and orders)
    __syncthreads();
    if (threadIdx.x == 0) {
        volatile unsigned* vph = &g_barphase;
        unsigned ph = *vph;
        if (atomicAdd(&g_barcnt, 1u) == (unsigned)nb - 1u) {
            g_barcnt = 0;
            __threadfence();
            *vph = ph + 1u;
        } else {
            while (*vph == ph) { }
        }
    }
    __syncthreads();
    __threadfence();          // acquire: CCTL.IVALL invalidates L1D (gpu-scope fence)
}

// ---------------- helpers ----------------
__device__ __forceinline__ unsigned f2tf(float x) {
    unsigned u; asm("cvt.rna.tf32.f32 %0, %1;" : "=r"(u) : "f"(x)); return u;
}
__device__ __forceinline__ void mma_tf32(float* d, const unsigned* a, const unsigned* b) {
    asm volatile("mma.sync.aligned.m16n8k8.row.col.f32.tf32.tf32.f32 "
        "{%0,%1,%2,%3}, {%4,%5,%6,%7}, {%8,%9}, {%0,%1,%2,%3};\n"
        : "+f"(d[0]), "+f"(d[1]), "+f"(d[2]), "+f"(d[3])
        : "r"(a[0]), "r"(a[1]), "r"(a[2]), "r"(a[3]), "r"(b[0]), "r"(b[1]));
}

// 32x32 tf32 GEMM tile, 256 threads (8 warps, 16x8 warp tiles), BK=32 double-buffered.
// C[m,n] = epi(sum_{k in [kbeg,kbeg+klen)} X[m,k]*W[n,k] (+ bias[n] if !PARTIAL)).
#define SK 36
template<int EPI, int PARTIAL>
__device__ __forceinline__ void gemm_tile(
        const float* __restrict__ X, const float* __restrict__ W,
        const float* __restrict__ bias, float* __restrict__ C,
        int m0, int n0, int N, int K, int kbeg, int klen, float* smemf) {
    unsigned* Xs = (unsigned*)smemf;            // [2][32][SK]
    unsigned* Ws = (unsigned*)smemf + 2*32*SK;  // [2][32][SK]
    __syncthreads();                            // smem reuse fence vs prior job
    int tid = threadIdx.x;
    int lane = tid & 31, wid = tid >> 5;
    int wm = wid & 1, wn = wid >> 1;            // 2 x 4 warp grid
    int r = lane >> 2, cq = lane & 3;
    int nk = klen >> 5;
    int lrow = tid >> 3;                        // 0..31
    int lkq  = (tid & 7) * 4;                   // 0..28
    const float* xg = X + (size_t)(m0 + lrow) * K + kbeg + lkq;
    const float* wg = W + (size_t)(n0 + lrow) * K + kbeg + lkq;

    float acc[4] = {};
    {
        float4 a = *reinterpret_cast<const float4*>(xg);
        float4 b = *reinterpret_cast<const float4*>(wg);
        uint4 ua = {f2tf(a.x), f2tf(a.y), f2tf(a.z), f2tf(a.w)};
        uint4 ub = {f2tf(b.x), f2tf(b.y), f2tf(b.z), f2tf(b.w)};
        *reinterpret_cast<uint4*>(&Xs[(0*32 + lrow)*SK + lkq]) = ua;
        *reinterpret_cast<uint4*>(&Ws[(0*32 + lrow)*SK + lkq]) = ub;
    }
    __syncthreads();

    int buf = 0;
    for (int kt = 0; kt < nk; ++kt) {
        float4 pa, pb;
        if (kt + 1 < nk) {
            pa = *reinterpret_cast<const float4*>(xg + (kt+1)*32);
            pb = *reinterpret_cast<const float4*>(wg + (kt+1)*32);
        }
        #pragma unroll
        for (int ks = 0; ks < 4; ++ks) {
            unsigned af[4], bf[2];
            int mr = wm*16 + r;
            af[0] = Xs[(buf*32 + mr)*SK + ks*8 + cq];
            af[1] = Xs[(buf*32 + mr + 8)*SK + ks*8 + cq];
            af[2] = Xs[(buf*32 + mr)*SK + ks*8 + cq + 4];
            af[3] = Xs[(buf*32 + mr + 8)*SK + ks*8 + cq + 4];
            int nr = wn*8 + r;
            bf[0] = Ws[(buf*32 + nr)*SK + ks*8 + cq];
            bf[1] = Ws[(buf*32 + nr)*SK + ks*8 + cq + 4];
            mma_tf32(acc, af, bf);
        }
        if (kt + 1 < nk) {
            uint4 ua = {f2tf(pa.x), f2tf(pa.y), f2tf(pa.z), f2tf(pa.w)};
            uint4 ub = {f2tf(pb.x), f2tf(pb.y), f2tf(pb.z), f2tf(pb.w)};
            *reinterpret_cast<uint4*>(&Xs[((buf^1)*32 + lrow)*SK + lkq]) = ua;
            *reinterpret_cast<uint4*>(&Ws[((buf^1)*32 + lrow)*SK + lkq]) = ub;
            __syncthreads();
            buf ^= 1;
        }
    }

    int m = m0 + wm*16 + r;
    int n = n0 + wn*8 + cq*2;
    if (PARTIAL) {
        #pragma unroll
        for (int half = 0; half < 2; ++half)
            *reinterpret_cast<float2*>(&C[(size_t)(m + half*8)*N + n]) =
                make_float2(acc[half*2], acc[half*2+1]);
    } else {
        #pragma unroll
        for (int half = 0; half < 2; ++half) {
            float v0 = acc[half*2+0] + bias[n];
            float v1 = acc[half*2+1] + bias[n+1];
            if (EPI == 1) { v0 = fmaxf(v0, 0.f); v1 = fmaxf(v1, 0.f); }
            if (EPI == 2) {
                v0 = 0.5f*v0*(1.f + erff(v0*0.70710678118654752f));
                v1 = 0.5f*v1*(1.f + erff(v1*0.70710678118654752f));
            }
            *reinterpret_cast<float2*>(&C[(size_t)(m + half*8)*N + n]) = make_float2(v0, v1);
        }
    }
}

// attention job: jb = qc (0..7) + 8*bh (0..15). 256 threads.
#define AQ_OFF 0
#define AK_OFF (16*68)
#define AV_OFF (AK_OFF + 128*68)
#define AP_OFF (AV_OFF + 128*68)
#define ATT_SMEM ((AP_OFF + 16*129)*4)
__device__ __forceinline__ void attn_job(const float* __restrict__ qkv,
                                         const int* __restrict__ mask,
                                         float* __restrict__ o, int jb, float* sm) {
    __syncthreads();                           // smem reuse fence
    int tid = threadIdx.x;
    int qc = jb & 7, bh = jb >> 3;
    int b = bh >> 2, h = bh & 3;

    const float4* src = reinterpret_cast<const float4*>(qkv);
    {
        int row = tid >> 4, d4 = tid & 15;
        float4 v = src[((size_t)(b*128 + qc*16 + row)*768 + h*64) / 4 + d4];
        *reinterpret_cast<float4*>(&sm[AQ_OFF + row*68 + d4*4]) = v;
    }
    #pragma unroll
    for (int it = 0; it < 8; ++it) {
        int e = it*256 + tid;
        int row = e >> 4, d4 = e & 15;
        float4 k = src[((size_t)(b*128 + row)*768 + 256 + h*64) / 4 + d4];
        float4 v = src[((size_t)(b*128 + row)*768 + 512 + h*64) / 4 + d4];
        *reinterpret_cast<float4*>(&sm[AK_OFF + row*68 + d4*4]) = k;
        *reinterpret_cast<float4*>(&sm[AV_OFF + row*68 + d4*4]) = v;
    }
    __syncthreads();

    int q = tid >> 4;
    int kb = tid & 15;
    float s[8];
    #pragma unroll
    for (int i = 0; i < 8; ++i) {
        int k = kb + 16*i;
        const float4* qp = reinterpret_cast<const float4*>(&sm[AQ_OFF + q*68]);
        const float4* kp = reinterpret_cast<const float4*>(&sm[AK_OFF + k*68]);
        float acc = 0.f;
        #pragma unroll
        for (int d4 = 0; d4 < 16; ++d4) {
            float4 a = qp[d4], c = kp[d4];
            acc += a.x*c.x + a.y*c.y + a.z*c.z + a.w*c.w;
        }
        acc *= 0.125f;
        if (mask[b*128 + k] == 0) acc = -1e9f;
        s[i] = acc;
    }
    float mx = s[0];
    #pragma unroll
    for (int i = 1; i < 8; ++i) mx = fmaxf(mx, s[i]);
    #pragma unroll
    for (int off = 1; off < 16; off <<= 1)
        mx = fmaxf(mx, __shfl_xor_sync(0xFFFFFFFFu, mx, off));
    float sum = 0.f;
    #pragma unroll
    for (int i = 0; i < 8; ++i) { s[i] = __expf(s[i] - mx); sum += s[i]; }
    #pragma unroll
    for (int off = 1; off < 16; off <<= 1)
        sum += __shfl_xor_sync(0xFFFFFFFFu, sum, off);
    float inv = 1.f / sum;
    #pragma unroll
    for (int i = 0; i < 8; ++i)
        sm[AP_OFF + q*129 + kb + 16*i] = s[i] * inv;
    __syncthreads();

    int dg = tid & 15;
    float4 acc4 = {0.f, 0.f, 0.f, 0.f};
    const float* Pr = &sm[AP_OFF + q*129];
    #pragma unroll 4
    for (int k = 0; k < 128; ++k) {
        float p = Pr[k];
        float4 v = *reinterpret_cast<const float4*>(&sm[AV_OFF + k*68 + dg*4]);
        acc4.x += p*v.x; acc4.y += p*v.y; acc4.z += p*v.z; acc4.w += p*v.w;
    }
    size_t orow = (size_t)(b*128 + qc*16 + q)*256 + h*64 + dg*4;
    *reinterpret_cast<float4*>(&o[orow]) = acc4;
}

// warp-per-row residual + (partials) + bias + LayerNorm. job covers rows job*8..job*8+7.
__device__ __forceinline__ void ln_rows8(const float* __restrict__ P,
                                         const float* __restrict__ bias,
                                         float* __restrict__ x,
                                         const float* __restrict__ g,
                                         const float* __restrict__ b,
                                         int job, int parts) {
    int wid = threadIdx.x >> 5, lane = threadIdx.x & 31;
    int row = job*8 + wid;
    size_t base = (size_t)row * 256;
    float h[8]; float s1 = 0.f, s2 = 0.f;
    #pragma unroll
    for (int i = 0; i < 8; ++i) {
        int d = lane + i*32;
        float s = bias ? bias[d] : 0.f;
        for (int p = 0; p < parts; ++p) s += P[(size_t)p*TOK*DM + base + d];
        h[i] = x[base + d] + s;
        s1 += h[i]; s2 += h[i]*h[i];
    }
    #pragma unroll
    for (int off = 16; off > 0; off >>= 1) {
        s1 += __shfl_xor_sync(0xFFFFFFFFu, s1, off);
        s2 += __shfl_xor_sync(0xFFFFFFFFu, s2, off);
    }
    float m = s1 * (1.f/256.f);
    float var = s2 * (1.f/256.f) - m*m;
    float inv = rsqrtf(var + 1e-5f);
    #pragma unroll
    for (int i = 0; i < 8; ++i) {
        int d = lane + i*32;
        x[base + d] = (h[i] - m) * inv * g[d] + b[d];
    }
}

// warp-per-row pe: j = jb*8 + warp
__device__ __forceinline__ void pe_job(const float* __restrict__ sp,
                                       const float* __restrict__ W,
                                       const float* __restrict__ bias,
                                       float* __restrict__ pe, int jb) {
    int warp = threadIdx.x >> 5, lane = threadIdx.x & 31;
    int j = jb*8 + warp;
    const float4* w4 = reinterpret_cast<const float4*>(W + (size_t)j * 256);
    float4 w0 = w4[lane];
    float4 w1 = w4[lane + 32];
    int k0 = lane * 4, k1 = (lane + 32) * 4;
    float acc[4];
    #pragma unroll
    for (int b = 0; b < 4; ++b) {
        const float* p = &sp[b*256];
        acc[b] = w0.x*p[k0] + w0.y*p[k0+1] + w0.z*p[k0+2] + w0.w*p[k0+3]
               + w1.x*p[k1] + w1.y*p[k1+1] + w1.z*p[k1+2] + w1.w*p[k1+3];
    }
    #pragma unroll
    for (int b = 0; b < 4; ++b)
        #pragma unroll
        for (int off = 16; off > 0; off >>= 1)
            acc[b] += __shfl_xor_sync(0xFFFFFFFFu, acc[b], off);
    if (lane < 4) pe[(size_t)lane * PEROW + j] = acc[lane] + bias[j];
}

// ---------------- persistent mega-kernel ----------------
#define GBLK 148
__global__ __launch_bounds__(256) void fused_main(
    const int* __restrict__ ids, const int* __restrict__ amask, const float* __restrict__ E,
    const float* __restrict__ qkvw, const float* __restrict__ qkvb,
    const float* __restrict__ ow, const float* __restrict__ ob,
    const float* __restrict__ ln1g, const float* __restrict__ ln1b,
    const float* __restrict__ f1w, const float* __restrict__ f1b,
    const float* __restrict__ f2w, const float* __restrict__ f2b,
    const float* __restrict__ ln2g, const float* __restrict__ ln2b,
    const float* __restrict__ projw, const float* __restrict__ projb,
    const float* __restrict__ a1w, const float* __restrict__ a1b,
    const float* __restrict__ a2w, const float* __restrict__ a2b,
    const float* __restrict__ bw1, const float* __restrict__ bb1,
    const float* __restrict__ bw2, const float* __restrict__ bb2,
    float* x, float* qkvbuf, float* attnbuf, float* ff1, float* part,
    float* pooled, float* pe, float* dechA, float* dechB, float* Ab, float* Bb) {
    extern __shared__ float sm[];
    const int G = gridDim.x, bid = blockIdx.x, tid = threadIdx.x;

    // embed
    for (int e = bid*256 + tid; e < TOK*64; e += G*256) {
        int tok = e >> 6;
        reinterpret_cast<float4*>(x)[e] =
            reinterpret_cast<const float4*>(E)[(size_t)ids[tok]*64 + (e & 63)];
    }
    gsync(G);

    for (int l = 0; l < 3; ++l) {
        const float* Wq = qkvw + (size_t)l*768*256;
        for (int jb = bid; jb < 384; jb += G) {
            int nt = jb % 24, mt = jb / 24;
            gemm_tile<0,0>(x, Wq, qkvb + l*768, qkvbuf, mt*32, nt*32, 768, 256, 0, 256, sm);
        }
        gsync(G);
        for (int jb = bid; jb < 128; jb += G) attn_job(qkvbuf, amask, attnbuf, jb, sm);
        gsync(G);
        const float* Wo = ow + (size_t)l*256*256;
        for (int jb = bid; jb < 128; jb += G) {
            int nt = jb & 7, mt = jb >> 3;
            gemm_tile<0,0>(attnbuf, Wo, ob + l*256, part, mt*32, nt*32, 256, 256, 0, 256, sm);
        }
        gsync(G);
        for (int jb = bid; jb < 64; jb += G)
            ln_rows8(part, nullptr, x, ln1g + l*256, ln1b + l*256, jb, 1);
        gsync(G);
        const float* W1 = f1w + (size_t)l*2048*256;
        for (int jb = bid; jb < 1024; jb += G) {
            int nt = jb & 63, mt = jb >> 6;
            gemm_tile<1,0>(x, W1, f1b + l*2048, ff1, mt*32, nt*32, 2048, 256, 0, 256, sm);
        }
        gsync(G);
        const float* W2 = f2w + (size_t)l*256*2048;
        for (int jb = bid; jb < 256; jb += G) {
            int z = jb >> 7, t2 = jb & 127;
            int nt = t2 & 7, mt = t2 >> 3;
            gemm_tile<0,1>(ff1, W2, nullptr, part + (size_t)z*TOK*DM,
                           mt*32, nt*32, 256, 2048, z*1024, 1024, sm);
        }
        gsync(G);
        for (int jb = bid; jb < 64; jb += G)
            ln_rows8(part, f2b + l*256, x, ln2g + l*256, ln2b + l*256, jb, 2);
        gsync(G);
    }

    // pool (blocks 0..3)
    if (bid < 4) {
        int b = bid, d = tid;
        float s = 0.f, den = 0.f;
        for (int t = 0; t < 128; ++t) {
            float am = (float)amask[b*128 + t];
            s += x[(size_t)(b*128 + t)*256 + d] * am;
            den += am;
        }
        pooled[b*256 + d] = s / fmaxf(den, 1.0f);
    }
    gsync(G);

    // pe: stage pooled into smem, then warp-per-row over 114688 rows
    for (int i = tid; i < 1024; i += 256) sm[i] = pooled[i];
    __syncthreads();
    for (int jb = bid; jb < PEROW/8; jb += G) pe_job(sm, projw, projb, pe, jb);
    gsync(G);

    // decoder stage 1: pe(896x512) -> dech(896x256), gelu. jobs: 2 sets x 8 x 28
    for (int jb = bid; jb < 448; jb += G) {
        int set = (jb >= 224);
        int t = jb - set*224;
        int nt = t & 7, mt = t >> 3;
        if (!set) gemm_tile<2,0>(pe, a1w, a1b, dechA, mt*32, nt*32, 256, 512, 0, 512, sm);
        else      gemm_tile<2,0>(pe, bw1, bb1, dechB, mt*32, nt*32, 256, 512, 0, 512, sm);
    }
    gsync(G);
    // decoder stage 2: dech(896x256) -> Ab/Bb(896x1024). jobs: 2 sets x 32 x 28
    for (int jb = bid; jb < 1792; jb += G) {
        int set = (jb >= 896);
        int t = jb - set*896;
        int nt = t & 31, mt = t >> 5;
        if (!set) gemm_tile<0,0>(dechA, a2w, a2b, Ab, mt*32, nt*32, 1024, 256, 0, 256, sm);
        else      gemm_tile<0,0>(dechB, bw2, bb2, Bb, mt*32, nt*32, 1024, 256, 0, 256, sm);
    }
}

// ---- unified writer: 5 regions in one launch ----
#define NB_A0 12288
#define NB_A1 2048
#define NB_B0 1536
#define NB_B1 512
#define NB_B2 1024
__device__ __forceinline__ void wr_A(const float4* Ab4, const float* scales,
                                     float4* out, int bx, int nI, int ind4, int mode,
                                     int tid) {
    int r = bx & 15;
    int i = (bx >> 4) % nI;
    int b = (bx >> 4) / nI;
    int p = (mode == 0) ? (i/6)*7 + (i%6) : i*7 + 6;
    float s = scales[2*p];
    float4 v = Ab4[(size_t)(b*224 + p)*256 + r*16 + (tid & 15)];
    v.x *= s; v.y *= s; v.z *= s; v.w *= s;
    size_t base = ((size_t)(b*nI + i)*16 + r) * ind4;
    for (int c4 = tid; c4 < ind4; c4 += 256)
        __stcs(&out[base + c4], v);
}
__device__ __forceinline__ void wr_B(const float4* Bb4, const float* scales,
                                     float4* out, int bx, int nI, int cnt, int nSplit,
                                     int mode, int tid) {
    int sp = bx % nSplit;
    int i = (bx / nSplit) % nI;
    int b = (bx / nSplit) / nI;
    int p;
    if (mode == 0)      p = (i/3)*7 + (i%3)*3;
    else if (mode == 1) p = (i/2)*7 + 1 + (i%2);
    else                p = (i/2)*7 + 4 + (i%2);
    float s = scales[2*p + 1];
    float4 v = Bb4[(size_t)(b*224 + p)*256 + tid];
    v.x *= s; v.y *= s; v.z *= s; v.w *= s;
    size_t base = (size_t)(b*nI + i) * ((size_t)cnt * nSplit) + (size_t)sp * cnt;
    for (int f = tid; f < cnt; f += 256)
        __stcs(&out[base + f], v);
}
__global__ __launch_bounds__(256) void write_all(
        const float4* __restrict__ Ab4, const float4* __restrict__ Bb4,
        const float* __restrict__ scales, float* __restrict__ outf) {
    int bx = blockIdx.x;
    int tid = threadIdx.x;
    if (bx < NB_A0) { wr_A(Ab4, scales, (float4*)outf, bx, 192, 4096/4, 0, tid); return; }
    bx -= NB_A0;
    if (bx < NB_A1) { wr_A(Ab4, scales, (float4*)(outf + OFF_AINT), bx, 32, 11008/4, 1, tid); return; }
    bx -= NB_A1;
    if (bx < NB_B0) { wr_B(Bb4, scales, (float4*)(outf + OFF_BHID), bx, 96, 4096, 4, 0, tid); return; }
    bx -= NB_B0;
    if (bx < NB_B1) { wr_B(Bb4, scales, (float4*)(outf + OFF_BKV), bx, 64, 2048, 2, 1, tid); return; }
    bx -= NB_B1;
    wr_B(Bb4, scales, (float4*)(outf + OFF_BINT), bx, 64, 11008, 4, 2, tid);
}

// ---------------- launch ----------------
extern "C" void kernel_launch(void* const* d_in, const int* in_sizes, int n_in,
                              void* d_out, int out_size) {
    const int*   ids   = (const int*)d_in[0];
    const int*   amask = (const int*)d_in[1];
    const float* E     = (const float*)d_in[2];
    const float* qkvw  = (const float*)d_in[3];
    const float* qkvb  = (const float*)d_in[4];
    const float* ow    = (const float*)d_in[5];
    const float* ob    = (const float*)d_in[6];
    const float* ln1g  = (const float*)d_in[7];
    const float* ln1b  = (const float*)d_in[8];
    const float* f1w   = (const float*)d_in[9];
    const float* f1b   = (const float*)d_in[10];
    const float* f2w   = (const float*)d_in[11];
    const float* f2b   = (const float*)d_in[12];
    const float* ln2g  = (const float*)d_in[13];
    const float* ln2b  = (const float*)d_in[14];
    const float* projw = (const float*)d_in[15];
    const float* projb = (const float*)d_in[16];
    const float* a1w   = (const float*)d_in[17];
    const float* a1b   = (const float*)d_in[18];
    const float* a2w   = (const float*)d_in[19];
    const float* a2b   = (const float*)d_in[20];
    const float* bw1   = (const float*)d_in[21];
    const float* bb1   = (const float*)d_in[22];
    const float* bw2   = (const float*)d_in[23];
    const float* bb2   = (const float*)d_in[24];
    const float* scales= (const float*)d_in[25];

    static int init = 0;
    if (!init) {
        cudaFuncSetAttribute(fused_main, cudaFuncAttributeMaxDynamicSharedMemorySize, ATT_SMEM);
        init = 1;
    }

    float* S = nullptr;
    cudaGetSymbolAddress((void**)&S, g_scratch);
    float* x     = S + S_X;
    float* qkvb_ = S + S_QKV;
    float* attn  = S + S_ATTN;
    float* ff1   = S + S_FF1;
    float* pool  = S + S_POOL;
    float* pe    = S + S_PE;
    float* dechA = S + S_DECHA;
    float* dechB = S + S_DECHB;
    float* Ab    = S + S_AB;
    float* Bb    = S + S_BB;
    float* part  = S + S_PART;
    float* out   = (float*)d_out;

    fused_main<<<GBLK, 256, ATT_SMEM>>>(
        ids, amask, E, qkvw, qkvb, ow, ob, ln1g, ln1b, f1w, f1b, f2w, f2b,
        ln2g, ln2b, projw, projb, a1w, a1b, a2w, a2b, bw1, bb1, bw2, bb2,
        x, qkvb_, attn, ff1, part, pool, pe, dechA, dechB, Ab, Bb);

    write_all<<<NB_A0 + NB_A1 + NB_B0 + NB_B1 + NB_B2, 256>>>(
        (const float4*)Ab, (const float4*)Bb, scales, out);
}

// round 6
// speedup vs baseline: 1.7795x; 1.7795x over previous
#include <cuda_runtime.h>
#include <cuda_bf16.h>
#include <cstdint>
#include <cstddef>

// ---------------- problem constants ----------------
#define BSZ   4
#define SEQ   128
#define TOK   (BSZ*SEQ)        // 512
#define DM    256
#define FF    2048
#define PP    224
#define PED   512
#define PEROW (PP*PED)         // 114688

// output region sizes (floats)
#define SZ_AHID (4LL*192*16*4096)
#define SZ_AINT (4LL*32*16*11008)
#define SZ_BHID (4LL*96*4096*16)
#define SZ_BKV  (4LL*64*1024*16)
#define OFF_AINT (SZ_AHID)
#define OFF_BHID (SZ_AHID+SZ_AINT)
#define OFF_BKV  (OFF_BHID+SZ_BHID)
#define OFF_BINT (OFF_BKV+SZ_BKV)

// ---------------- scratch ----------------
#define S_X     0
#define S_QKV   (S_X    + TOK*DM)
#define S_ATTN  (S_QKV  + TOK*3*DM)
#define S_FF1   (S_ATTN + TOK*DM)
#define S_POOL  (S_FF1  + TOK*FF)
#define S_PE    (S_POOL + BSZ*DM)
#define S_DECHA (S_PE   + BSZ*PEROW)
#define S_DECHB (S_DECHA + 896*DM)
#define S_AB    (S_DECHB + 896*DM)
#define S_BB    (S_AB   + 896*1024)
#define S_PART  (S_BB   + 896*1024)
#define S_TOTAL (S_PART + 4*TOK*DM)

__device__ float g_scratch[S_TOTAL];

// ---------------- PDL helpers ----------------
__device__ __forceinline__ void gdc_wait()   { asm volatile("griddepcontrol.wait;" ::: "memory"); }
__device__ __forceinline__ void gdc_launch() { asm volatile("griddepcontrol.launch_dependents;" ::: "memory"); }

// ---------------- math helpers ----------------
__device__ __forceinline__ unsigned f2tf(float x) {
    unsigned u; asm("cvt.rna.tf32.f32 %0, %1;" : "=r"(u) : "f"(x)); return u;
}
__device__ __forceinline__ void mma_tf32(float* d, const unsigned* a, const unsigned* b) {
    asm volatile("mma.sync.aligned.m16n8k8.row.col.f32.tf32.tf32.f32 "
        "{%0,%1,%2,%3}, {%4,%5,%6,%7}, {%8,%9}, {%0,%1,%2,%3};\n"
        : "+f"(d[0]), "+f"(d[1]), "+f"(d[2]), "+f"(d[3])
        : "r"(a[0]), "r"(a[1]), "r"(a[2]), "r"(a[3]), "r"(b[0]), "r"(b[1]));
}

// ---------------- kernels ----------------

__global__ void embed_kernel(const int* __restrict__ ids, const float* __restrict__ E,
                             float* __restrict__ x) {
    int tok = blockIdx.x;
    int t = threadIdx.x;
    gdc_wait();
    int id = ids[tok];
    reinterpret_cast<float4*>(x)[tok*64 + t] =
        reinterpret_cast<const float4*>(E)[(size_t)id*64 + t];
    gdc_launch();
}

// C[m,n] = epi( sum_k X[m,k]*W[n,k] + bias[n] ), tf32 tensor cores.
// BM=BN=32, BK=32, 128 threads (4 warps, 16x16 warp tile).
// BATCH=1: blockIdx.z selects problem set A vs B.
// BATCH=0 && gridDim.z>1: split-K partials into Cpart (no bias/epi).
#define SK 36
template<int EPI, int BATCH>
__global__ __launch_bounds__(128) void gemm32(
        const float* __restrict__ X, const float* __restrict__ W,
        const float* __restrict__ bias, float* __restrict__ C,
        float* __restrict__ Cpart,
        const float* __restrict__ X2, const float* __restrict__ W2,
        const float* __restrict__ bias2, float* __restrict__ C2,
        int M, int N, int K) {
    __shared__ unsigned Xs[2][32][SK];
    __shared__ unsigned Ws[2][32][SK];
    int tid = threadIdx.x;
    int lane = tid & 31, wid = tid >> 5;
    int wm = wid & 1, wn = wid >> 1;
    int r = lane >> 2, cq = lane & 3;
    int m0 = blockIdx.y * 32, n0 = blockIdx.x * 32;
    int kbeg, nk;
    if (BATCH) {
        if (blockIdx.z) { X = X2; W = W2; bias = bias2; C = C2; }
        kbeg = 0; nk = K >> 5;
    } else {
        int kchunk = K / gridDim.z;
        kbeg = blockIdx.z * kchunk;
        nk = kchunk >> 5;
    }

    int lrow = tid >> 2;              // 0..31
    int lkq  = (tid & 3) * 4;         // 0,4,8,12
    const float* xg = X + (size_t)(m0 + lrow) * K + kbeg + lkq;
    const float* wg = W + (size_t)(n0 + lrow) * K + kbeg + lkq;

    gdc_wait();                       // prologue (index math) overlapped with producer

    float acc[2][4] = {};

    {
        float4 a0 = *reinterpret_cast<const float4*>(xg);
        float4 a1 = *reinterpret_cast<const float4*>(xg + 16);
        float4 b0 = *reinterpret_cast<const float4*>(wg);
        float4 b1 = *reinterpret_cast<const float4*>(wg + 16);
        uint4 ua0 = {f2tf(a0.x), f2tf(a0.y), f2tf(a0.z), f2tf(a0.w)};
        uint4 ua1 = {f2tf(a1.x), f2tf(a1.y), f2tf(a1.z), f2tf(a1.w)};
        uint4 ub0 = {f2tf(b0.x), f2tf(b0.y), f2tf(b0.z), f2tf(b0.w)};
        uint4 ub1 = {f2tf(b1.x), f2tf(b1.y), f2tf(b1.z), f2tf(b1.w)};
        *reinterpret_cast<uint4*>(&Xs[0][lrow][lkq])      = ua0;
        *reinterpret_cast<uint4*>(&Xs[0][lrow][lkq + 16]) = ua1;
        *reinterpret_cast<uint4*>(&Ws[0][lrow][lkq])      = ub0;
        *reinterpret_cast<uint4*>(&Ws[0][lrow][lkq + 16]) = ub1;
    }
    __syncthreads();

    int buf = 0;
    for (int kt = 0; kt < nk; ++kt) {
        float4 pa0, pa1, pb0, pb1;
        if (kt + 1 < nk) {
            pa0 = *reinterpret_cast<const float4*>(xg + (kt+1)*32);
            pa1 = *reinterpret_cast<const float4*>(xg + (kt+1)*32 + 16);
            pb0 = *reinterpret_cast<const float4*>(wg + (kt+1)*32);
            pb1 = *reinterpret_cast<const float4*>(wg + (kt+1)*32 + 16);
        }
        #pragma unroll
        for (int ks = 0; ks < 4; ++ks) {
            unsigned af[4];
            int mr = wm*16 + r;
            af[0] = Xs[buf][mr][ks*8 + cq];
            af[1] = Xs[buf][mr + 8][ks*8 + cq];
            af[2] = Xs[buf][mr][ks*8 + cq + 4];
            af[3] = Xs[buf][mr + 8][ks*8 + cq + 4];
            #pragma unroll
            for (int nt = 0; nt < 2; ++nt) {
                unsigned bf[2];
                int nr = wn*16 + nt*8 + r;
                bf[0] = Ws[buf][nr][ks*8 + cq];
                bf[1] = Ws[buf][nr][ks*8 + cq + 4];
                mma_tf32(acc[nt], af, bf);
            }
        }
        if (kt + 1 < nk) {
            uint4 ua0 = {f2tf(pa0.x), f2tf(pa0.y), f2tf(pa0.z), f2tf(pa0.w)};
            uint4 ua1 = {f2tf(pa1.x), f2tf(pa1.y), f2tf(pa1.z), f2tf(pa1.w)};
            uint4 ub0 = {f2tf(pb0.x), f2tf(pb0.y), f2tf(pb0.z), f2tf(pb0.w)};
            uint4 ub1 = {f2tf(pb1.x), f2tf(pb1.y), f2tf(pb1.z), f2tf(pb1.w)};
            *reinterpret_cast<uint4*>(&Xs[buf^1][lrow][lkq])      = ua0;
            *reinterpret_cast<uint4*>(&Xs[buf^1][lrow][lkq + 16]) = ua1;
            *reinterpret_cast<uint4*>(&Ws[buf^1][lrow][lkq])      = ub0;
            *reinterpret_cast<uint4*>(&Ws[buf^1][lrow][lkq + 16]) = ub1;
            __syncthreads();
            buf ^= 1;
        }
    }

    int m = m0 + wm*16 + r;
    if (!BATCH && gridDim.z > 1) {
        float* P = Cpart + (size_t)blockIdx.z * M * N;
        #pragma unroll
        for (int nt = 0; nt < 2; ++nt) {
            int n = n0 + wn*16 + nt*8 + cq*2;
            #pragma unroll
            for (int half = 0; half < 2; ++half)
                *reinterpret_cast<float2*>(&P[(size_t)(m + half*8)*N + n]) =
                    make_float2(acc[nt][half*2], acc[nt][half*2+1]);
        }
    } else {
        #pragma unroll
        for (int nt = 0; nt < 2; ++nt) {
            int n = n0 + wn*16 + nt*8 + cq*2;
            #pragma unroll
            for (int half = 0; half < 2; ++half) {
                float v0 = acc[nt][half*2+0] + bias[n];
                float v1 = acc[nt][half*2+1] + bias[n+1];
                if (EPI == 1) { v0 = fmaxf(v0, 0.f); v1 = fmaxf(v1, 0.f); }
                if (EPI == 2) {
                    v0 = 0.5f*v0*(1.f + erff(v0*0.70710678118654752f));
                    v1 = 0.5f*v1*(1.f + erff(v1*0.70710678118654752f));
                }
                *reinterpret_cast<float2*>(&C[(size_t)(m + half*8)*N + n]) = make_float2(v0, v1);
            }
        }
    }
    gdc_launch();
}

// sum split-K partials + bias + residual, then LayerNorm; writes x in place.
__global__ void ksplit_ln(const float* __restrict__ P, const float* __restrict__ bias,
                          float* __restrict__ x, const float* __restrict__ g,
                          const float* __restrict__ b, int parts) {
    int row = blockIdx.x, d = threadIdx.x;
    __shared__ float r1[256], r2[256];
    size_t idx = (size_t)row*256 + d;
    gdc_wait();
    float s = bias[d];
    for (int p = 0; p < parts; ++p) s += P[(size_t)p*TOK*DM + idx];
    float h = x[idx] + s;
    r1[d] = h; r2[d] = h*h; __syncthreads();
    for (int st = 128; st > 0; st >>= 1) {
        if (d < st) { r1[d] += r1[d+st]; r2[d] += r2[d+st]; }
        __syncthreads();
    }
    float m = r1[0] * (1.f/256.f);
    float var = r2[0] * (1.f/256.f) - m*m;
    x[idx] = (h - m) * rsqrtf(var + 1e-5f) * g[d] + b[d];
    gdc_launch();
}

// Fused attention: block = (q-chunk of 16, b*4+h). 256 threads, grid (8,16).
#define AQ_OFF 0
#define AK_OFF (16*68)
#define AV_OFF (AK_OFF + 128*68)
#define AP_OFF (AV_OFF + 128*68)
#define ATT_SMEM ((AP_OFF + 16*129)*4)
__global__ void attn_fused(const float* __restrict__ qkv, const int* __restrict__ mask,
                           float* __restrict__ o) {
    extern __shared__ float sm[];
    int tid = threadIdx.x;
    int qc = blockIdx.x;
    int bh = blockIdx.y;
    int b = bh >> 2, h = bh & 3;

    gdc_wait();
    const float4* src = reinterpret_cast<const float4*>(qkv);
    {
        int row = tid >> 4, d4 = tid & 15;
        float4 v = src[((size_t)(b*128 + qc*16 + row)*768 + h*64) / 4 + d4];
        *reinterpret_cast<float4*>(&sm[AQ_OFF + row*68 + d4*4]) = v;
    }
    #pragma unroll
    for (int it = 0; it < 8; ++it) {
        int e = it*256 + tid;
        int row = e >> 4, d4 = e & 15;
        float4 k = src[((size_t)(b*128 + row)*768 + 256 + h*64) / 4 + d4];
        float4 v = src[((size_t)(b*128 + row)*768 + 512 + h*64) / 4 + d4];
        *reinterpret_cast<float4*>(&sm[AK_OFF + row*68 + d4*4]) = k;
        *reinterpret_cast<float4*>(&sm[AV_OFF + row*68 + d4*4]) = v;
    }
    __syncthreads();

    int q = tid >> 4;
    int kb = tid & 15;
    float s[8];
    #pragma unroll
    for (int i = 0; i < 8; ++i) {
        int k = kb + 16*i;
        const float4* qp = reinterpret_cast<const float4*>(&sm[AQ_OFF + q*68]);
        const float4* kp = reinterpret_cast<const float4*>(&sm[AK_OFF + k*68]);
        float acc = 0.f;
        #pragma unroll
        for (int d4 = 0; d4 < 16; ++d4) {
            float4 a = qp[d4], c = kp[d4];
            acc += a.x*c.x + a.y*c.y + a.z*c.z + a.w*c.w;
        }
        acc *= 0.125f;
        if (mask[b*128 + k] == 0) acc = -1e9f;
        s[i] = acc;
    }
    float mx = s[0];
    #pragma unroll
    for (int i = 1; i < 8; ++i) mx = fmaxf(mx, s[i]);
    #pragma unroll
    for (int off = 1; off < 16; off <<= 1)
        mx = fmaxf(mx, __shfl_xor_sync(0xFFFFFFFFu, mx, off));
    float sum = 0.f;
    #pragma unroll
    for (int i = 0; i < 8; ++i) { s[i] = __expf(s[i] - mx); sum += s[i]; }
    #pragma unroll
    for (int off = 1; off < 16; off <<= 1)
        sum += __shfl_xor_sync(0xFFFFFFFFu, sum, off);
    float inv = 1.f / sum;
    #pragma unroll
    for (int i = 0; i < 8; ++i)
        sm[AP_OFF + q*129 + kb + 16*i] = s[i] * inv;
    __syncthreads();

    int dg = tid & 15;
    float4 acc4 = {0.f, 0.f, 0.f, 0.f};
    const float* Pr = &sm[AP_OFF + q*129];
    #pragma unroll 4
    for (int k = 0; k < 128; ++k) {
        float p = Pr[k];
        float4 v = *reinterpret_cast<const float4*>(&sm[AV_OFF + k*68 + dg*4]);
        acc4.x += p*v.x; acc4.y += p*v.y; acc4.z += p*v.z; acc4.w += p*v.w;
    }
    size_t orow = (size_t)(b*128 + qc*16 + q)*256 + h*64 + dg*4;
    *reinterpret_cast<float4*>(&o[orow]) = acc4;
    gdc_launch();
}

__global__ void pool_kernel(const float* __restrict__ x, const int* __restrict__ mask,
                            float* __restrict__ pooled) {
    int b = blockIdx.x, d = threadIdx.x;
    gdc_wait();
    float s = 0.f, den = 0.f;
    for (int t = 0; t < 128; ++t) {
        float am = (float)mask[b*128 + t];
        s += x[(size_t)(b*128 + t)*256 + d] * am;
        den += am;
    }
    pooled[b*256 + d] = s / fmaxf(den, 1.0f);
    gdc_launch();
}

__global__ void pe_kernel(const float* __restrict__ pooled, const float* __restrict__ W,
                          const float* __restrict__ bias, float* __restrict__ pe) {
    __shared__ float sp[1024];
    int t = threadIdx.x;
    int warp = t >> 5, lane = t & 31;
    int j = blockIdx.x * 8 + warp;
    // prologue: weight rows are inputs, fetch before wait to overlap with producers
    const float4* w4 = reinterpret_cast<const float4*>(W + (size_t)j * 256);
    float4 w0 = w4[lane];
    float4 w1 = w4[lane + 32];
    gdc_wait();
    #pragma unroll
    for (int i = 0; i < 4; ++i) sp[t + i*256] = pooled[t + i*256];
    __syncthreads();
    int k0 = lane * 4, k1 = (lane + 32) * 4;
    float acc[4];
    #pragma unroll
    for (int b = 0; b < 4; ++b) {
        const float* p = &sp[b*256];
        acc[b] = w0.x*p[k0] + w0.y*p[k0+1] + w0.z*p[k0+2] + w0.w*p[k0+3]
               + w1.x*p[k1] + w1.y*p[k1+1] + w1.z*p[k1+2] + w1.w*p[k1+3];
    }
    #pragma unroll
    for (int b = 0; b < 4; ++b)
        #pragma unroll
        for (int off = 16; off > 0; off >>= 1)
            acc[b] += __shfl_xor_sync(0xFFFFFFFFu, acc[b], off);
    if (lane < 4) pe[(size_t)lane * PEROW + j] = acc[lane] + bias[j];
    gdc_launch();
}

// ---- unified writer: 5 regions in one launch ----
#define NB_A0 12288
#define NB_A1 2048
#define NB_B0 1536
#define NB_B1 512
#define NB_B2 1024
__device__ __forceinline__ void wr_A(const float4* Ab4, const float* scales,
                                     float4* out, int bx, int nI, int ind4, int mode,
                                     int tid) {
    int r = bx & 15;
    int i = (bx >> 4) % nI;
    int b = (bx >> 4) / nI;
    int p = (mode == 0) ? (i/6)*7 + (i%6) : i*7 + 6;
    float s = scales[2*p];
    float4 v = Ab4[(size_t)(b*224 + p)*256 + r*16 + (tid & 15)];
    v.x *= s; v.y *= s; v.z *= s; v.w *= s;
    size_t base = ((size_t)(b*nI + i)*16 + r) * ind4;
    for (int c4 = tid; c4 < ind4; c4 += 256)
        __stcs(&out[base + c4], v);
}
__device__ __forceinline__ void wr_B(const float4* Bb4, const float* scales,
                                     float4* out, int bx, int nI, int cnt, int nSplit,
                                     int mode, int tid) {
    int sp = bx % nSplit;
    int i = (bx / nSplit) % nI;
    int b = (bx / nSplit) / nI;
    int p;
    if (mode == 0)      p = (i/3)*7 + (i%3)*3;
    else if (mode == 1) p = (i/2)*7 + 1 + (i%2);
    else                p = (i/2)*7 + 4 + (i%2);
    float s = scales[2*p + 1];
    float4 v = Bb4[(size_t)(b*224 + p)*256 + tid];
    v.x *= s; v.y *= s; v.z *= s; v.w *= s;
    size_t base = (size_t)(b*nI + i) * ((size_t)cnt * nSplit) + (size_t)sp * cnt;
    for (int f = tid; f < cnt; f += 256)
        __stcs(&out[base + f], v);
}
__global__ __launch_bounds__(256) void write_all(
        const float4* __restrict__ Ab4, const float4* __restrict__ Bb4,
        const float* __restrict__ scales, float* __restrict__ outf) {
    int bx = blockIdx.x;
    int tid = threadIdx.x;
    gdc_wait();
    if (bx < NB_A0) { wr_A(Ab4, scales, (float4*)outf, bx, 192, 4096/4, 0, tid); return; }
    bx -= NB_A0;
    if (bx < NB_A1) { wr_A(Ab4, scales, (float4*)(outf + OFF_AINT), bx, 32, 11008/4, 1, tid); return; }
    bx -= NB_A1;
    if (bx < NB_B0) { wr_B(Bb4, scales, (float4*)(outf + OFF_BHID), bx, 96, 4096, 4, 0, tid); return; }
    bx -= NB_B0;
    if (bx < NB_B1) { wr_B(Bb4, scales, (float4*)(outf + OFF_BKV), bx, 64, 2048, 2, 1, tid); return; }
    bx -= NB_B1;
    wr_B(Bb4, scales, (float4*)(outf + OFF_BINT), bx, 64, 11008, 4, 2, tid);
}

// ---------------- host: PDL launch helper ----------------
template<typename F, typename... Args>
static inline void launch_pdl(F f, dim3 g, dim3 b, size_t smem, Args... args) {
    cudaLaunchConfig_t cfg = {};
    cfg.gridDim = g;
    cfg.blockDim = b;
    cfg.dynamicSmemBytes = smem;
    cfg.stream = 0;
    cudaLaunchAttribute attr[1];
    attr[0].id = cudaLaunchAttributeProgrammaticStreamSerialization;
    attr[0].val.programmaticStreamSerializationAllowed = 1;
    cfg.attrs = attr;
    cfg.numAttrs = 1;
    cudaLaunchKernelEx(&cfg, f, args...);
}

// ---------------- launch ----------------
extern "C" void kernel_launch(void* const* d_in, const int* in_sizes, int n_in,
                              void* d_out, int out_size) {
    const int*   ids   = (const int*)d_in[0];
    const int*   amask = (const int*)d_in[1];
    const float* E     = (const float*)d_in[2];
    const float* qkvw  = (const float*)d_in[3];
    const float* qkvb  = (const float*)d_in[4];
    const float* ow    = (const float*)d_in[5];
    const float* ob    = (const float*)d_in[6];
    const float* ln1g  = (const float*)d_in[7];
    const float* ln1b  = (const float*)d_in[8];
    const float* f1w   = (const float*)d_in[9];
    const float* f1b   = (const float*)d_in[10];
    const float* f2w   = (const float*)d_in[11];
    const float* f2b   = (const float*)d_in[12];
    const float* ln2g  = (const float*)d_in[13];
    const float* ln2b  = (const float*)d_in[14];
    const float* projw = (const float*)d_in[15];
    const float* projb = (const float*)d_in[16];
    const float* a1w   = (const float*)d_in[17];
    const float* a1b   = (const float*)d_in[18];
    const float* a2w   = (const float*)d_in[19];
    const float* a2b   = (const float*)d_in[20];
    const float* bw1   = (const float*)d_in[21];
    const float* bb1   = (const float*)d_in[22];
    const float* bw2   = (const float*)d_in[23];
    const float* bb2   = (const float*)d_in[24];
    const float* scales= (const float*)d_in[25];

    cudaFuncSetAttribute(attn_fused, cudaFuncAttributeMaxDynamicSharedMemorySize, ATT_SMEM);

    float* S = nullptr;
    cudaGetSymbolAddress((void**)&S, g_scratch);
    float* x     = S + S_X;
    float* qkv   = S + S_QKV;
    float* attn  = S + S_ATTN;
    float* ff1   = S + S_FF1;
    float* pool  = S + S_POOL;
    float* pe    = S + S_PE;
    float* dechA = S + S_DECHA;
    float* dechB = S + S_DECHB;
    float* Ab    = S + S_AB;
    float* Bb    = S + S_BB;
    float* part  = S + S_PART;
    float* out   = (float*)d_out;
    const float* FNUL = nullptr;
    float* NUL = nullptr;

    launch_pdl(embed_kernel, dim3(TOK), dim3(64), 0, ids, E, x);

    for (int l = 0; l < 3; ++l) {
        launch_pdl(gemm32<0,0>, dim3(24, 16, 1), dim3(128), 0,
                   (const float*)x, qkvw + (size_t)l*768*256, qkvb + l*768,
                   qkv, NUL, FNUL, FNUL, FNUL, NUL, TOK, 768, 256);
        launch_pdl(attn_fused, dim3(8, 16), dim3(256), (size_t)ATT_SMEM,
                   (const float*)qkv, amask, attn);
        launch_pdl(gemm32<0,0>, dim3(8, 16, 2), dim3(128), 0,
                   (const float*)attn, ow + (size_t)l*256*256, FNUL,
                   NUL, part, FNUL, FNUL, FNUL, NUL, TOK, 256, 256);
        launch_pdl(ksplit_ln, dim3(TOK), dim3(256), 0,
                   (const float*)part, ob + l*256, x, ln1g + l*256, ln1b + l*256, 2);
        launch_pdl(gemm32<1,0>, dim3(64, 16, 1), dim3(128), 0,
                   (const float*)x, f1w + (size_t)l*2048*256, f1b + l*2048,
                   ff1, NUL, FNUL, FNUL, FNUL, NUL, TOK, 2048, 256);
        launch_pdl(gemm32<0,0>, dim3(8, 16, 4), dim3(128), 0,
                   (const float*)ff1, f2w + (size_t)l*256*2048, FNUL,
                   NUL, part, FNUL, FNUL, FNUL, NUL, TOK, 256, 2048);
        launch_pdl(ksplit_ln, dim3(TOK), dim3(256), 0,
                   (const float*)part, f2b + l*256, x, ln2g + l*256, ln2b + l*256, 4);
    }

    launch_pdl(pool_kernel, dim3(BSZ), dim3(256), 0, (const float*)x, amask, pool);
    launch_pdl(pe_kernel, dim3(PEROW/8), dim3(256), 0,
               (const float*)pool, projw, projb, pe);

    launch_pdl(gemm32<2,1>, dim3(8, 28, 2), dim3(128), 0,
               (const float*)pe, a1w, a1b, dechA, NUL,
               (const float*)pe, bw1, bb1, dechB, 896, 256, 512);
    launch_pdl(gemm32<0,1>, dim3(32, 28, 2), dim3(128), 0,
               (const float*)dechA, a2w, a2b, Ab, NUL,
               (const float*)dechB, bw2, bb2, Bb, 896, 1024, 256);

    launch_pdl(write_all, dim3(NB_A0 + NB_A1 + NB_B0 + NB_B1 + NB_B2), dim3(256), 0,
               (const float4*)Ab, (const float4*)Bb, scales, out);
}

// round 7
// speedup vs baseline: 2.0509x; 1.1525x over previous
#include <cuda_runtime.h>
#include <cuda_bf16.h>
#include <cstdint>
#include <cstddef>

// ---------------- problem constants ----------------
#define BSZ   4
#define SEQ   128
#define TOK   (BSZ*SEQ)        // 512
#define DM    256
#define FF    2048
#define PP    224
#define PED   512
#define PEROW (PP*PED)         // 114688

// output region sizes (floats)
#define SZ_AHID (4LL*192*16*4096)
#define SZ_AINT (4LL*32*16*11008)
#define SZ_BHID (4LL*96*4096*16)
#define SZ_BKV  (4LL*64*1024*16)
#define OFF_AINT (SZ_AHID)
#define OFF_BHID (SZ_AHID+SZ_AINT)
#define OFF_BKV  (OFF_BHID+SZ_BHID)
#define OFF_BINT (OFF_BKV+SZ_BKV)

// ---------------- scratch ----------------
#define S_X     0
#define S_QKV   (S_X    + TOK*DM)
#define S_ATTN  (S_QKV  + TOK*3*DM)
#define S_FF1   (S_ATTN + TOK*DM)
#define S_POOL  (S_FF1  + TOK*FF)
#define S_PE    (S_POOL + BSZ*DM)
#define S_DECHA (S_PE   + BSZ*PEROW)
#define S_DECHB (S_DECHA + 896*DM)
#define S_AB    (S_DECHB + 896*DM)
#define S_BB    (S_AB   + 896*1024)
#define S_PART  (S_BB   + 896*1024)
#define S_TOTAL (S_PART + 4*TOK*DM)

__device__ float g_scratch[S_TOTAL];

// ---------------- PDL helpers ----------------
__device__ __forceinline__ void gdc_wait()   { asm volatile("griddepcontrol.wait;" ::: "memory"); }
__device__ __forceinline__ void gdc_launch() { asm volatile("griddepcontrol.launch_dependents;" ::: "memory"); }

// ---------------- math helpers ----------------
__device__ __forceinline__ unsigned f2tf(float x) {
    unsigned u; asm("cvt.rna.tf32.f32 %0, %1;" : "=r"(u) : "f"(x)); return u;
}
__device__ __forceinline__ void mma_tf32(float* d, const unsigned* a, const unsigned* b) {
    asm volatile("mma.sync.aligned.m16n8k8.row.col.f32.tf32.tf32.f32 "
        "{%0,%1,%2,%3}, {%4,%5,%6,%7}, {%8,%9}, {%0,%1,%2,%3};\n"
        : "+f"(d[0]), "+f"(d[1]), "+f"(d[2]), "+f"(d[3])
        : "r"(a[0]), "r"(a[1]), "r"(a[2]), "r"(a[3]), "r"(b[0]), "r"(b[1]));
}
__device__ __forceinline__ void cp16(float* smem_dst, const float* gsrc) {
    unsigned s = (unsigned)__cvta_generic_to_shared(smem_dst);
    asm volatile("cp.async.ca.shared.global [%0], [%1], 16;" :: "r"(s), "l"(gsrc));
}
__device__ __forceinline__ void cp_commit() { asm volatile("cp.async.commit_group;"); }
template<int N>
__device__ __forceinline__ void cp_wait() { asm volatile("cp.async.wait_group %0;" :: "n"(N)); }

// ---------------- kernels ----------------

__global__ void embed_kernel(const int* __restrict__ ids, const float* __restrict__ E,
                             float* __restrict__ x) {
    int tok = blockIdx.x;
    int t = threadIdx.x;
    gdc_wait();
    int id = ids[tok];
    reinterpret_cast<float4*>(x)[tok*64 + t] =
        reinterpret_cast<const float4*>(E)[(size_t)id*64 + t];
    gdc_launch();
}

// C[m,n] = epi( sum_k X[m,k]*W[n,k] + bias[n] ), tf32 tensor cores.
// BM=BN=32, BK=32, 128 threads (4 warps, 16x16 warp tile), 4-stage cp.async pipeline.
// BATCH=1: blockIdx.z selects problem set A vs B.
// BATCH=0 && gridDim.z>1: split-K partials into Cpart (no bias/epi).
#define SK 36
#define STG 4
template<int EPI, int BATCH>
__global__ __launch_bounds__(128) void gemm32(
        const float* __restrict__ X, const float* __restrict__ W,
        const float* __restrict__ bias, float* __restrict__ C,
        float* __restrict__ Cpart,
        const float* __restrict__ X2, const float* __restrict__ W2,
        const float* __restrict__ bias2, float* __restrict__ C2,
        int M, int N, int K) {
    __shared__ float Xs[STG][32][SK];
    __shared__ float Ws[STG][32][SK];
    int tid = threadIdx.x;
    int lane = tid & 31, wid = tid >> 5;
    int wm = wid & 1, wn = wid >> 1;
    int r = lane >> 2, cq = lane & 3;
    int m0 = blockIdx.y * 32, n0 = blockIdx.x * 32;
    int kbeg, nk;
    if (BATCH) {
        if (blockIdx.z) { X = X2; W = W2; bias = bias2; C = C2; }
        kbeg = 0; nk = K >> 5;
    } else {
        int kchunk = K / gridDim.z;
        kbeg = blockIdx.z * kchunk;
        nk = kchunk >> 5;
    }

    int row2 = tid >> 3;              // 0..15
    int colq = (tid & 7) * 4;         // 0..28
    const float* xg = X + (size_t)(m0 + row2) * K + kbeg + colq;
    const float* wg = W + (size_t)(n0 + row2) * K + kbeg + colq;
    size_t rstep = (size_t)16 * K;

    gdc_wait();                       // producer data only touched after this

    // prologue: issue STG-1 stages (pad with empty groups)
    #pragma unroll
    for (int s = 0; s < STG-1; ++s) {
        if (s < nk) {
            const float* xp = xg + s*32;
            const float* wp = wg + s*32;
            cp16(&Xs[s][row2][colq],      xp);
            cp16(&Xs[s][row2+16][colq],   xp + rstep);
            cp16(&Ws[s][row2][colq],      wp);
            cp16(&Ws[s][row2+16][colq],   wp + rstep);
        }
        cp_commit();
    }

    float acc[2][4] = {};

    for (int kt = 0; kt < nk; ++kt) {
        int buf = kt & (STG-1);
        cp_wait<STG-2>();
        __syncthreads();
        // issue next stage (overwrites buffer consumed at kt-1; sync above protects it)
        {
            int ks2 = kt + STG - 1;
            if (ks2 < nk) {
                int b2 = ks2 & (STG-1);
                const float* xp = xg + ks2*32;
                const float* wp = wg + ks2*32;
                cp16(&Xs[b2][row2][colq],      xp);
                cp16(&Xs[b2][row2+16][colq],   xp + rstep);
                cp16(&Ws[b2][row2][colq],      wp);
                cp16(&Ws[b2][row2+16][colq],   wp + rstep);
            }
            cp_commit();
        }
        #pragma unroll
        for (int ks = 0; ks < 4; ++ks) {
            unsigned af[4];
            int mr = wm*16 + r;
            af[0] = f2tf(Xs[buf][mr][ks*8 + cq]);
            af[1] = f2tf(Xs[buf][mr + 8][ks*8 + cq]);
            af[2] = f2tf(Xs[buf][mr][ks*8 + cq + 4]);
            af[3] = f2tf(Xs[buf][mr + 8][ks*8 + cq + 4]);
            #pragma unroll
            for (int nt = 0; nt < 2; ++nt) {
                unsigned bf[2];
                int nr = wn*16 + nt*8 + r;
                bf[0] = f2tf(Ws[buf][nr][ks*8 + cq]);
                bf[1] = f2tf(Ws[buf][nr][ks*8 + cq + 4]);
                mma_tf32(acc[nt], af, bf);
            }
        }
    }

    int m = m0 + wm*16 + r;
    if (!BATCH && gridDim.z > 1) {
        float* P = Cpart + (size_t)blockIdx.z * M * N;
        #pragma unroll
        for (int nt = 0; nt < 2; ++nt) {
            int n = n0 + wn*16 + nt*8 + cq*2;
            #pragma unroll
            for (int half = 0; half < 2; ++half)
                *reinterpret_cast<float2*>(&P[(size_t)(m + half*8)*N + n]) =
                    make_float2(acc[nt][half*2], acc[nt][half*2+1]);
        }
    } else {
        #pragma unroll
        for (int nt = 0; nt < 2; ++nt) {
            int n = n0 + wn*16 + nt*8 + cq*2;
            #pragma unroll
            for (int half = 0; half < 2; ++half) {
                float v0 = acc[nt][half*2+0] + bias[n];
                float v1 = acc[nt][half*2+1] + bias[n+1];
                if (EPI == 1) { v0 = fmaxf(v0, 0.f); v1 = fmaxf(v1, 0.f); }
                if (EPI == 2) {
                    v0 = 0.5f*v0*(1.f + erff(v0*0.70710678118654752f));
                    v1 = 0.5f*v1*(1.f + erff(v1*0.70710678118654752f));
                }
                *reinterpret_cast<float2*>(&C[(size_t)(m + half*8)*N + n]) = make_float2(v0, v1);
            }
        }
    }
    gdc_launch();
}

// sum split-K partials + bias + residual, then LayerNorm; writes x in place.
__global__ void ksplit_ln(const float* __restrict__ P, const float* __restrict__ bias,
                          float* __restrict__ x, const float* __restrict__ g,
                          const float* __restrict__ b, int parts) {
    int row = blockIdx.x, d = threadIdx.x;
    __shared__ float r1[256], r2[256];
    size_t idx = (size_t)row*256 + d;
    gdc_wait();
    float s = bias[d];
    for (int p = 0; p < parts; ++p) s += P[(size_t)p*TOK*DM + idx];
    float h = x[idx] + s;
    r1[d] = h; r2[d] = h*h; __syncthreads();
    for (int st = 128; st > 0; st >>= 1) {
        if (d < st) { r1[d] += r1[d+st]; r2[d] += r2[d+st]; }
        __syncthreads();
    }
    float m = r1[0] * (1.f/256.f);
    float var = r2[0] * (1.f/256.f) - m*m;
    x[idx] = (h - m) * rsqrtf(var + 1e-5f) * g[d] + b[d];
    gdc_launch();
}

// Fused attention: block = (q-chunk of 16, b*4+h). 256 threads, grid (8,16).
#define AQ_OFF 0
#define AK_OFF (16*68)
#define AV_OFF (AK_OFF + 128*68)
#define AP_OFF (AV_OFF + 128*68)
#define ATT_SMEM ((AP_OFF + 16*129)*4)
__global__ void attn_fused(const float* __restrict__ qkv, const int* __restrict__ mask,
                           float* __restrict__ o) {
    extern __shared__ float sm[];
    int tid = threadIdx.x;
    int qc = blockIdx.x;
    int bh = blockIdx.y;
    int b = bh >> 2, h = bh & 3;

    gdc_wait();
    const float4* src = reinterpret_cast<const float4*>(qkv);
    {
        int row = tid >> 4, d4 = tid & 15;
        float4 v = src[((size_t)(b*128 + qc*16 + row)*768 + h*64) / 4 + d4];
        *reinterpret_cast<float4*>(&sm[AQ_OFF + row*68 + d4*4]) = v;
    }
    #pragma unroll
    for (int it = 0; it < 8; ++it) {
        int e = it*256 + tid;
        int row = e >> 4, d4 = e & 15;
        float4 k = src[((size_t)(b*128 + row)*768 + 256 + h*64) / 4 + d4];
        float4 v = src[((size_t)(b*128 + row)*768 + 512 + h*64) / 4 + d4];
        *reinterpret_cast<float4*>(&sm[AK_OFF + row*68 + d4*4]) = k;
        *reinterpret_cast<float4*>(&sm[AV_OFF + row*68 + d4*4]) = v;
    }
    __syncthreads();

    int q = tid >> 4;
    int kb = tid & 15;
    float s[8];
    #pragma unroll
    for (int i = 0; i < 8; ++i) {
        int k = kb + 16*i;
        const float4* qp = reinterpret_cast<const float4*>(&sm[AQ_OFF + q*68]);
        const float4* kp = reinterpret_cast<const float4*>(&sm[AK_OFF + k*68]);
        float acc = 0.f;
        #pragma unroll
        for (int d4 = 0; d4 < 16; ++d4) {
            float4 a = qp[d4], c = kp[d4];
            acc += a.x*c.x + a.y*c.y + a.z*c.z + a.w*c.w;
        }
        acc *= 0.125f;
        if (mask[b*128 + k] == 0) acc = -1e9f;
        s[i] = acc;
    }
    float mx = s[0];
    #pragma unroll
    for (int i = 1; i < 8; ++i) mx = fmaxf(mx, s[i]);
    #pragma unroll
    for (int off = 1; off < 16; off <<= 1)
        mx = fmaxf(mx, __shfl_xor_sync(0xFFFFFFFFu, mx, off));
    float sum = 0.f;
    #pragma unroll
    for (int i = 0; i < 8; ++i) { s[i] = __expf(s[i] - mx); sum += s[i]; }
    #pragma unroll
    for (int off = 1; off < 16; off <<= 1)
        sum += __shfl_xor_sync(0xFFFFFFFFu, sum, off);
    float inv = 1.f / sum;
    #pragma unroll
    for (int i = 0; i < 8; ++i)
        sm[AP_OFF + q*129 + kb + 16*i] = s[i] * inv;
    __syncthreads();

    int dg = tid & 15;
    float4 acc4 = {0.f, 0.f, 0.f, 0.f};
    const float* Pr = &sm[AP_OFF + q*129];
    #pragma unroll 4
    for (int k = 0; k < 128; ++k) {
        float p = Pr[k];
        float4 v = *reinterpret_cast<const float4*>(&sm[AV_OFF + k*68 + dg*4]);
        acc4.x += p*v.x; acc4.y += p*v.y; acc4.z += p*v.z; acc4.w += p*v.w;
    }
    size_t orow = (size_t)(b*128 + qc*16 + q)*256 + h*64 + dg*4;
    *reinterpret_cast<float4*>(&o[orow]) = acc4;
    gdc_launch();
}

// pool: grid 4, block 1024 (4 token-groups x 256 dims), 2-level reduce
__global__ __launch_bounds__(1024) void pool_kernel(
        const float* __restrict__ x, const int* __restrict__ mask,
        float* __restrict__ pooled) {
    __shared__ float red[1024];
    __shared__ float redden[1024];
    int b = blockIdx.x;
    int tid = threadIdx.x;
    int d = tid & 255, tg = tid >> 8;   // 4 groups of 32 tokens
    gdc_wait();
    float s = 0.f, den = 0.f;
    #pragma unroll 8
    for (int t = tg*32; t < tg*32 + 32; ++t) {
        float am = (float)mask[b*128 + t];
        s += x[(size_t)(b*128 + t)*256 + d] * am;
        den += am;
    }
    red[tid] = s; redden[tid] = den;
    __syncthreads();
    if (tg == 0) {
        s   = red[d] + red[d+256] + red[d+512] + red[d+768];
        den = redden[d] + redden[d+256] + redden[d+512] + redden[d+768];
        pooled[b*256 + d] = s / fmaxf(den, 1.0f);
    }
    gdc_launch();
}

__global__ void pe_kernel(const float* __restrict__ pooled, const float* __restrict__ W,
                          const float* __restrict__ bias, float* __restrict__ pe) {
    __shared__ float sp[1024];
    int t = threadIdx.x;
    int warp = t >> 5, lane = t & 31;
    int j = blockIdx.x * 8 + warp;
    // prologue: weight rows are kernel inputs; fetch before wait to overlap producers
    const float4* w4 = reinterpret_cast<const float4*>(W + (size_t)j * 256);
    float4 w0 = w4[lane];
    float4 w1 = w4[lane + 32];
    gdc_wait();
    #pragma unroll
    for (int i = 0; i < 4; ++i) sp[t + i*256] = pooled[t + i*256];
    __syncthreads();
    int k0 = lane * 4, k1 = (lane + 32) * 4;
    float acc[4];
    #pragma unroll
    for (int b = 0; b < 4; ++b) {
        const float* p = &sp[b*256];
        acc[b] = w0.x*p[k0] + w0.y*p[k0+1] + w0.z*p[k0+2] + w0.w*p[k0+3]
               + w1.x*p[k1] + w1.y*p[k1+1] + w1.z*p[k1+2] + w1.w*p[k1+3];
    }
    #pragma unroll
    for (int b = 0; b < 4; ++b)
        #pragma unroll
        for (int off = 16; off > 0; off >>= 1)
            acc[b] += __shfl_xor_sync(0xFFFFFFFFu, acc[b], off);
    if (lane < 4) pe[(size_t)lane * PEROW + j] = acc[lane] + bias[j];
    gdc_launch();
}

// ---- unified writer: 5 regions in one launch ----
#define NB_A0 12288
#define NB_A1 2048
#define NB_B0 1536
#define NB_B1 512
#define NB_B2 1024
__device__ __forceinline__ void wr_A(const float4* Ab4, const float* scales,
                                     float4* out, int bx, int nI, int ind4, int mode,
                                     int tid) {
    int r = bx & 15;
    int i = (bx >> 4) % nI;
    int b = (bx >> 4) / nI;
    int p = (mode == 0) ? (i/6)*7 + (i%6) : i*7 + 6;
    float s = scales[2*p];
    float4 v = Ab4[(size_t)(b*224 + p)*256 + r*16 + (tid & 15)];
    v.x *= s; v.y *= s; v.z *= s; v.w *= s;
    size_t base = ((size_t)(b*nI + i)*16 + r) * ind4;
    for (int c4 = tid; c4 < ind4; c4 += 256)
        __stcs(&out[base + c4], v);
}
__device__ __forceinline__ void wr_B(const float4* Bb4, const float* scales,
                                     float4* out, int bx, int nI, int cnt, int nSplit,
                                     int mode, int tid) {
    int sp = bx % nSplit;
    int i = (bx / nSplit) % nI;
    int b = (bx / nSplit) / nI;
    int p;
    if (mode == 0)      p = (i/3)*7 + (i%3)*3;
    else if (mode == 1) p = (i/2)*7 + 1 + (i%2);
    else                p = (i/2)*7 + 4 + (i%2);
    float s = scales[2*p + 1];
    float4 v = Bb4[(size_t)(b*224 + p)*256 + tid];
    v.x *= s; v.y *= s; v.z *= s; v.w *= s;
    size_t base = (size_t)(b*nI + i) * ((size_t)cnt * nSplit) + (size_t)sp * cnt;
    for (int f = tid; f < cnt; f += 256)
        __stcs(&out[base + f], v);
}
__global__ __launch_bounds__(256) void write_all(
        const float4* __restrict__ Ab4, const float4* __restrict__ Bb4,
        const float* __restrict__ scales, float* __restrict__ outf) {
    int bx = blockIdx.x;
    int tid = threadIdx.x;
    gdc_wait();
    if (bx < NB_A0) { wr_A(Ab4, scales, (float4*)outf, bx, 192, 4096/4, 0, tid); return; }
    bx -= NB_A0;
    if (bx < NB_A1) { wr_A(Ab4, scales, (float4*)(outf + OFF_AINT), bx, 32, 11008/4, 1, tid); return; }
    bx -= NB_A1;
    if (bx < NB_B0) { wr_B(Bb4, scales, (float4*)(outf + OFF_BHID), bx, 96, 4096, 4, 0, tid); return; }
    bx -= NB_B0;
    if (bx < NB_B1) { wr_B(Bb4, scales, (float4*)(outf + OFF_BKV), bx, 64, 2048, 2, 1, tid); return; }
    bx -= NB_B1;
    wr_B(Bb4, scales, (float4*)(outf + OFF_BINT), bx, 64, 11008, 4, 2, tid);
}

// ---------------- host: PDL launch helper ----------------
template<typename F, typename... Args>
static inline void launch_pdl(F f, dim3 g, dim3 b, size_t smem, Args... args) {
    cudaLaunchConfig_t cfg = {};
    cfg.gridDim = g;
    cfg.blockDim = b;
    cfg.dynamicSmemBytes = smem;
    cfg.stream = 0;
    cudaLaunchAttribute attr[1];
    attr[0].id = cudaLaunchAttributeProgrammaticStreamSerialization;
    attr[0].val.programmaticStreamSerializationAllowed = 1;
    cfg.attrs = attr;
    cfg.numAttrs = 1;
    cudaLaunchKernelEx(&cfg, f, args...);
}

// ---------------- launch ----------------
extern "C" void kernel_launch(void* const* d_in, const int* in_sizes, int n_in,
                              void* d_out, int out_size) {
    const int*   ids   = (const int*)d_in[0];
    const int*   amask = (const int*)d_in[1];
    const float* E     = (const float*)d_in[2];
    const float* qkvw  = (const float*)d_in[3];
    const float* qkvb  = (const float*)d_in[4];
    const float* ow    = (const float*)d_in[5];
    const float* ob    = (const float*)d_in[6];
    const float* ln1g  = (const float*)d_in[7];
    const float* ln1b  = (const float*)d_in[8];
    const float* f1w   = (const float*)d_in[9];
    const float* f1b   = (const float*)d_in[10];
    const float* f2w   = (const float*)d_in[11];
    const float* f2b   = (const float*)d_in[12];
    const float* ln2g  = (const float*)d_in[13];
    const float* ln2b  = (const float*)d_in[14];
    const float* projw = (const float*)d_in[15];
    const float* projb = (const float*)d_in[16];
    const float* a1w   = (const float*)d_in[17];
    const float* a1b   = (const float*)d_in[18];
    const float* a2w   = (const float*)d_in[19];
    const float* a2b   = (const float*)d_in[20];
    const float* bw1   = (const float*)d_in[21];
    const float* bb1   = (const float*)d_in[22];
    const float* bw2   = (const float*)d_in[23];
    const float* bb2   = (const float*)d_in[24];
    const float* scales= (const float*)d_in[25];

    cudaFuncSetAttribute(attn_fused, cudaFuncAttributeMaxDynamicSharedMemorySize, ATT_SMEM);

    float* S = nullptr;
    cudaGetSymbolAddress((void**)&S, g_scratch);
    float* x     = S + S_X;
    float* qkv   = S + S_QKV;
    float* attn  = S + S_ATTN;
    float* ff1   = S + S_FF1;
    float* pool  = S + S_POOL;
    float* pe    = S + S_PE;
    float* dechA = S + S_DECHA;
    float* dechB = S + S_DECHB;
    float* Ab    = S + S_AB;
    float* Bb    = S + S_BB;
    float* part  = S + S_PART;
    float* out   = (float*)d_out;
    const float* FNUL = nullptr;
    float* NUL = nullptr;

    launch_pdl(embed_kernel, dim3(TOK), dim3(64), 0, ids, E, x);

    for (int l = 0; l < 3; ++l) {
        launch_pdl(gemm32<0,0>, dim3(24, 16, 1), dim3(128), 0,
                   (const float*)x, qkvw + (size_t)l*768*256, qkvb + l*768,
                   qkv, NUL, FNUL, FNUL, FNUL, NUL, TOK, 768, 256);
        launch_pdl(attn_fused, dim3(8, 16), dim3(256), (size_t)ATT_SMEM,
                   (const float*)qkv, amask, attn);
        launch_pdl(gemm32<0,0>, dim3(8, 16, 2), dim3(128), 0,
                   (const float*)attn, ow + (size_t)l*256*256, FNUL,
                   NUL, part, FNUL, FNUL, FNUL, NUL, TOK, 256, 256);
        launch_pdl(ksplit_ln, dim3(TOK), dim3(256), 0,
                   (const float*)part, ob + l*256, x, ln1g + l*256, ln1b + l*256, 2);
        launch_pdl(gemm32<1,0>, dim3(64, 16, 1), dim3(128), 0,
                   (const float*)x, f1w + (size_t)l*2048*256, f1b + l*2048,
                   ff1, NUL, FNUL, FNUL, FNUL, NUL, TOK, 2048, 256);
        launch_pdl(gemm32<0,0>, dim3(8, 16, 4), dim3(128), 0,
                   (const float*)ff1, f2w + (size_t)l*256*2048, FNUL,
                   NUL, part, FNUL, FNUL, FNUL, NUL, TOK, 256, 2048);
        launch_pdl(ksplit_ln, dim3(TOK), dim3(256), 0,
                   (const float*)part, f2b + l*256, x, ln2g + l*256, ln2b + l*256, 4);
    }

    launch_pdl(pool_kernel, dim3(BSZ), dim3(1024), 0, (const float*)x, amask, pool);
    launch_pdl(pe_kernel, dim3(PEROW/8), dim3(256), 0,
               (const float*)pool, projw, projb, pe);

    launch_pdl(gemm32<2,1>, dim3(8, 28, 2), dim3(128), 0,
               (const float*)pe, a1w, a1b, dechA, NUL,
               (const float*)pe, bw1, bb1, dechB, 896, 256, 512);
    launch_pdl(gemm32<0,1>, dim3(32, 28, 2), dim3(128), 0,
               (const float*)dechA, a2w, a2b, Ab, NUL,
               (const float*)dechB, bw2, bb2, Bb, 896, 1024, 256);

    launch_pdl(write_all, dim3(NB_A0 + NB_A1 + NB_B0 + NB_B1 + NB_B2), dim3(256), 0,
               (const float4*)Ab, (const float4*)Bb, scales, out);
}